// round 13
// baseline (speedup 1.0000x reference)
#include <cuda_runtime.h>
#include <cuda_bf16.h>
#include <mma.h>

using namespace nvcuda;

// Problem constants (fixed by the reference setup)
constexpr int kN = 50000;
constexpr int kE = 200000;
constexpr int kM = 512;          // m = fin*fout = 512 for both layers
constexpr float kEps = 1e-5f;

// ---------------- persistent device scratch (no cudaMalloc allowed) ----------------
__device__ float g_agg0[kN * 32];            // layer0 scatter accumulator
__device__ float g_agg1[kN * 16];            // layer1 scatter accumulator
__device__ float g_deg[kN];                  // in-degree (shared by both layers)
__device__ float g_x1[kN * 32];              // layer0 output (post BN+lrelu)
__device__ float g_bn0[64];                  // layer0 per-channel sum / sumsq
__device__ float g_bn1[32];                  // layer1 per-channel sum / sumsq
__device__ __align__(16) __nv_bfloat16 g_W2bf0[kM * kM];
__device__ __align__(16) __nv_bfloat16 g_W2bf1[kM * kM];

// ---------------- utility kernels ----------------
__global__ void zero_kernel() {
    int idx = blockIdx.x * blockDim.x + threadIdx.x;
    int stride = gridDim.x * blockDim.x;
    for (int i = idx; i < kN * 32; i += stride) g_agg0[i] = 0.f;
    for (int i = idx; i < kN * 16; i += stride) g_agg1[i] = 0.f;
    for (int i = idx; i < kN; i += stride) g_deg[i] = 0.f;
    if (idx < 64) g_bn0[idx] = 0.f;
    if (idx < 32) g_bn1[idx] = 0.f;
}

__global__ void convert_kernel(const float* __restrict__ W2_0,
                               const float* __restrict__ W2_1) {
    int idx = blockIdx.x * blockDim.x + threadIdx.x;
    int stride = gridDim.x * blockDim.x;
    for (int i = idx; i < kM * kM; i += stride) {
        g_W2bf0[i] = __float2bfloat16(W2_0[i]);
        g_W2bf1[i] = __float2bfloat16(W2_1[i]);
    }
}

__global__ void deg_kernel(const int* __restrict__ dst) {
    int e = blockIdx.x * blockDim.x + threadIdx.x;
    if (e < kE) atomicAdd(&g_deg[dst[e]], 1.0f);
}

// ---------------- fused edge kernel ----------------
// Per CTA: 64 edges, 128 threads (4 warps), 2 CTAs/SM (smem <= ~113KB each).
// U = lrelu(ea@W1+b1) in SMEM (bf16); per input-feature i: GEMM
// [64,512]@[512,FOUT] (wmma bf16) with sB staged in K-halves of 256 to fit,
// fold msg += x[src][:,i] * (H_i + b2_i); atomically scatter msg to agg[dst].
template <int FIN, int FOUT>
__global__ __launch_bounds__(128, 2)
void edge_kernel(const float* __restrict__ x_in,
                 const float* __restrict__ ea,
                 const float* __restrict__ W1,
                 const float* __restrict__ b1,
                 const float* __restrict__ b2,
                 const int* __restrict__ src,
                 const int* __restrict__ dst) {
    constexpr int TE = 64;           // edges per CTA
    constexpr int NT = 128;          // threads
    constexpr int KH = 256;          // K-half rows staged per buffer
    constexpr int UPAD = 520;        // bf16 row stride for U
    constexpr int BPAD = FOUT + 8;   // bf16 row stride for B tile (16B-aligned rows)
    constexpr int CPAD = FOUT + 4;   // fp32 row stride for C scratch
    constexpr int SEGS = FOUT / 8;   // 16-byte segments per B row

    extern __shared__ char smem_raw[];
    __nv_bfloat16* sU = (__nv_bfloat16*)smem_raw;             // TE*UPAD
    __nv_bfloat16* sB = sU + TE * UPAD;                       // KH*BPAD
    float* sC   = (float*)(sB + KH * BPAD);                   // 4*16*CPAD
    float* sMsg = sC + 4 * 16 * CPAD;                         // TE*FOUT
    float* sXS  = sMsg + TE * FOUT;                           // TE*FIN
    float* sEA  = sXS + TE * FIN;                             // TE*8
    float* sB2  = sEA + TE * 8;                               // kM

    // device-global selection happens here, in device code
    const float* x = (FIN == 32) ? (const float*)g_x1 : x_in;
    float* agg = (FOUT == 32) ? (float*)g_agg0 : (float*)g_agg1;
    const __nv_bfloat16* W2bf = (FOUT == 32) ? (const __nv_bfloat16*)g_W2bf0
                                             : (const __nv_bfloat16*)g_W2bf1;

    int tid = threadIdx.x;
    int w = tid >> 5, lane = tid & 31;   // 4 warps; warp w owns rows [16w,16w+16)
    int e0 = blockIdx.x * TE;

    // stage edge_attr, gathered source features, b2; zero msg
    for (int idx = tid; idx < TE * 8; idx += NT) {
        int r = idx >> 3;
        sEA[idx] = ea[(e0 + r) * 8 + (idx & 7)];
    }
    for (int idx = tid; idx < TE * FIN; idx += NT) {
        int r = idx / FIN;
        sXS[idx] = x[src[e0 + r] * FIN + (idx % FIN)];
    }
    for (int idx = tid; idx < TE * FOUT; idx += NT) sMsg[idx] = 0.f;
    for (int idx = tid; idx < kM; idx += NT) sB2[idx] = b2[idx];
    __syncthreads();

    // U = lrelu(ea @ W1 + b1) -> bf16
    for (int idx = tid; idx < TE * kM; idx += NT) {
        int r = idx >> 9;
        int k = idx & 511;
        float v = b1[k];
        const float* eaR = sEA + r * 8;
#pragma unroll
        for (int j = 0; j < 8; j++) v += eaR[j] * W1[j * kM + k];
        v = (v >= 0.f) ? v : 0.01f * v;
        sU[r * UPAD + k] = __float2bfloat16(v);
    }
    // (first __syncthreads inside the h-loop covers sU readiness)

    for (int i = 0; i < FIN; i++) {
        wmma::fragment<wmma::accumulator, 16, 16, 16, float> cfr[FOUT / 16];
#pragma unroll
        for (int t = 0; t < FOUT / 16; t++) wmma::fill_fragment(cfr[t], 0.f);

        for (int h = 0; h < 2; h++) {
            __syncthreads();  // prev phase done reading sB
            // stage W2 rows [h*KH, h*KH+KH) x cols [i*FOUT, i*FOUT+FOUT), 16B at a time
            for (int idx = tid; idx < KH * SEGS; idx += NT) {
                int k = idx / SEGS;
                int seg = idx % SEGS;
                const uint4* srcp = (const uint4*)(W2bf + (h * KH + k) * kM + i * FOUT) + seg;
                *((uint4*)(sB + k * BPAD) + seg) = *srcp;
            }
            __syncthreads();

            const __nv_bfloat16* aBase = sU + (w * 16) * UPAD + h * KH;
            for (int k = 0; k < KH; k += 16) {
                wmma::fragment<wmma::matrix_a, 16, 16, 16, __nv_bfloat16, wmma::row_major> afr;
                wmma::load_matrix_sync(afr, aBase + k, UPAD);
#pragma unroll
                for (int t = 0; t < FOUT / 16; t++) {
                    wmma::fragment<wmma::matrix_b, 16, 16, 16, __nv_bfloat16, wmma::row_major> bfr;
                    wmma::load_matrix_sync(bfr, sB + k * BPAD + t * 16, BPAD);
                    wmma::mma_sync(cfr[t], afr, bfr, cfr[t]);
                }
            }
        }

        float* cW = sC + w * 16 * CPAD;
#pragma unroll
        for (int t = 0; t < FOUT / 16; t++)
            wmma::store_matrix_sync(cW + t * 16, cfr[t], CPAD, wmma::mem_row_major);
        __syncwarp();
        // msg[row, c] += xs[row, i] * (H_i[row, c] + b2[i*FOUT + c])
        // warp w exclusively owns rows [16w, 16w+16) -> no cross-warp race
        for (int idx = lane; idx < 16 * FOUT; idx += 32) {
            int r = idx / FOUT;
            int c = idx % FOUT;
            int row = w * 16 + r;
            sMsg[row * FOUT + c] += sXS[row * FIN + i] * (cW[r * CPAD + c] + sB2[i * FOUT + c]);
        }
        __syncwarp();
    }
    __syncthreads();

    // scatter-add messages at destination nodes
    for (int idx = tid; idx < TE * FOUT; idx += NT) {
        int r = idx / FOUT;
        atomicAdd(&agg[dst[e0 + r] * FOUT + (idx % FOUT)], sMsg[idx]);
    }
}

// ---------------- combine: v = agg/deg + x@root + bias; accumulate BN stats ----------------
template <int FIN, int FOUT>
__global__ void combine_kernel(const float* __restrict__ x_in,
                               const float* __restrict__ root,
                               const float* __restrict__ bias,
                               float* __restrict__ vout_param) {
    constexpr int NPB = 256 / FOUT;          // nodes per block-pass
    __shared__ float sroot[FIN * FOUT];
    __shared__ float sred[256];

    const float* agg = (FOUT == 32) ? (const float*)g_agg0 : (const float*)g_agg1;
    const float* x = (FIN == 32) ? (const float*)g_x1 : x_in;
    float* vout = (FOUT == 32) ? (float*)g_x1 : vout_param;
    float* bnsum = (FOUT == 32) ? (float*)g_bn0 : (float*)g_bn1;

    int tid = threadIdx.x;
    int o = tid % FOUT;
    int nl = tid / FOUT;
    for (int idx = tid; idx < FIN * FOUT; idx += 256) sroot[idx] = root[idx];
    __syncthreads();

    float s = 0.f, ss = 0.f;
    float bo = bias[o];
    int nblocks = kN / NPB;  // exact: 50000 % 8 == 0, % 16 == 0
    for (int nb = blockIdx.x; nb < nblocks; nb += gridDim.x) {
        int n = nb * NPB + nl;
        float v = agg[n * FOUT + o] / fmaxf(g_deg[n], 1.f);
        const float* xr = x + n * FIN;
#pragma unroll
        for (int i = 0; i < FIN; i++) v += xr[i] * sroot[i * FOUT + o];
        v += bo;
        vout[n * FOUT + o] = v;
        s += v;
        ss += v * v;
    }
    // block-reduce over the node dimension, per channel
    sred[tid] = s;
    __syncthreads();
    for (int m = NPB / 2; m > 0; m >>= 1) {
        if (nl < m) sred[tid] += sred[tid + m * FOUT];
        __syncthreads();
    }
    if (nl == 0) atomicAdd(&bnsum[o], sred[tid]);
    __syncthreads();
    sred[tid] = ss;
    __syncthreads();
    for (int m = NPB / 2; m > 0; m >>= 1) {
        if (nl < m) sred[tid] += sred[tid + m * FOUT];
        __syncthreads();
    }
    if (nl == 0) atomicAdd(&bnsum[FOUT + o], sred[tid]);
}

// ---------------- finalize: batchnorm (+ optional lrelu), in place ----------------
template <int FOUT, bool LRELU>
__global__ void finalize_kernel(float* __restrict__ v_param,
                                const float* __restrict__ gamma,
                                const float* __restrict__ beta) {
    float* v = (FOUT == 32) ? (float*)g_x1 : v_param;
    const float* bnsum = (FOUT == 32) ? (const float*)g_bn0 : (const float*)g_bn1;
    int idx = blockIdx.x * blockDim.x + threadIdx.x;
    if (idx >= kN * FOUT) return;
    int o = idx % FOUT;
    float mu = bnsum[o] * (1.f / kN);
    float var = bnsum[FOUT + o] * (1.f / kN) - mu * mu;
    float sc = rsqrtf(var + kEps) * gamma[o];
    float val = (v[idx] - mu) * sc + beta[o];
    if (LRELU) val = (val >= 0.f) ? val : 0.01f * val;
    v[idx] = val;
}

// ---------------- launch ----------------
extern "C" void kernel_launch(void* const* d_in, const int* in_sizes, int n_in,
                              void* d_out, int out_size) {
    (void)n_in; (void)out_size;
    // Input-order dispatch (confirmed: harness uses dict-insertion order;
    // keep signature-order fallback for robustness).
    const bool dictOrder = (in_sizes[2] == 2 * kE);
    const int wbase = dictOrder ? 3 : 2;      // index of W1_0
    const int eiIdx = dictOrder ? 2 : 18;     // index of edge_index

    const float* x      = (const float*)d_in[0];
    const float* ea     = (const float*)d_in[1];
    const float* W1_0   = (const float*)d_in[wbase + 0];
    const float* b1_0   = (const float*)d_in[wbase + 1];
    const float* W2_0   = (const float*)d_in[wbase + 2];
    const float* b2_0   = (const float*)d_in[wbase + 3];
    const float* root_0 = (const float*)d_in[wbase + 4];
    const float* bias_0 = (const float*)d_in[wbase + 5];
    const float* gamma_0 = (const float*)d_in[wbase + 6];
    const float* beta_0  = (const float*)d_in[wbase + 7];
    const float* W1_1   = (const float*)d_in[wbase + 8];
    const float* b1_1   = (const float*)d_in[wbase + 9];
    const float* W2_1   = (const float*)d_in[wbase + 10];
    const float* b2_1   = (const float*)d_in[wbase + 11];
    const float* root_1 = (const float*)d_in[wbase + 12];
    const float* bias_1 = (const float*)d_in[wbase + 13];
    const float* gamma_1 = (const float*)d_in[wbase + 14];
    const float* beta_1  = (const float*)d_in[wbase + 15];
    const int* ei = (const int*)d_in[eiIdx];
    const int* src = ei;
    const int* dst = ei + kE;
    float* out = (float*)d_out;

    // dynamic SMEM: TE=64, KH=256 staging. 2 CTAs/SM.
    constexpr int SMEM0 = 64 * 520 * 2 + 256 * 40 * 2 + 4 * 16 * 36 * 4 +
                          64 * 32 * 4 + 64 * 16 * 4 + 64 * 8 * 4 + kM * 4;  // 112640
    constexpr int SMEM1 = 64 * 520 * 2 + 256 * 24 * 2 + 4 * 16 * 20 * 4 +
                          64 * 16 * 4 + 64 * 32 * 4 + 64 * 8 * 4 + kM * 4;  // 100352
    cudaFuncSetAttribute(edge_kernel<16, 32>,
                         cudaFuncAttributeMaxDynamicSharedMemorySize, SMEM0);
    cudaFuncSetAttribute(edge_kernel<32, 16>,
                         cudaFuncAttributeMaxDynamicSharedMemorySize, SMEM1);

    constexpr int EDGE_BLOCKS = kE / 64;  // 3125, exact

    zero_kernel<<<2048, 256>>>();
    convert_kernel<<<1024, 256>>>(W2_0, W2_1);
    deg_kernel<<<(kE + 255) / 256, 256>>>(dst);

    // ---- layer 0 ----
    edge_kernel<16, 32><<<EDGE_BLOCKS, 128, SMEM0>>>(x, ea, W1_0, b1_0, b2_0, src, dst);
    combine_kernel<16, 32><<<1024, 256>>>(x, root_0, bias_0, nullptr);
    finalize_kernel<32, true><<<(kN * 32 + 255) / 256, 256>>>(nullptr, gamma_0, beta_0);

    // ---- layer 1 ----
    edge_kernel<32, 16><<<EDGE_BLOCKS, 128, SMEM1>>>(nullptr, ea, W1_1, b1_1, b2_1, src, dst);
    combine_kernel<32, 16><<<1024, 256>>>(nullptr, root_1, bias_1, out);
    finalize_kernel<16, false><<<(kN * 16 + 255) / 256, 256>>>(out, gamma_1, beta_1);
}

// round 17
// speedup vs baseline: 1.3300x; 1.3300x over previous
#include <cuda_runtime.h>
#include <cuda_bf16.h>
#include <mma.h>

using namespace nvcuda;

// Problem constants (fixed by the reference setup)
constexpr int kN = 50000;
constexpr int kE = 200000;
constexpr int kM = 512;          // m = fin*fout = 512 for both layers
constexpr float kEps = 1e-5f;

// ---------------- persistent device scratch (no cudaMalloc allowed) ----------------
__device__ float g_agg0[kN * 32];            // layer0 scatter accumulator
__device__ float g_agg1[kN * 16];            // layer1 scatter accumulator
__device__ float g_deg[kN];                  // in-degree (shared by both layers)
__device__ float g_x1[kN * 32];              // layer0 output (post BN+lrelu)
__device__ float g_bn0[64];                  // layer0 per-channel sum / sumsq
__device__ float g_bn1[32];                  // layer1 per-channel sum / sumsq
__device__ __align__(16) __nv_bfloat16 g_W2bf0[kM * kM];
__device__ __align__(16) __nv_bfloat16 g_W2bf1[kM * kM];

// ---------------- utility kernels ----------------
__global__ void zero_kernel() {
    int idx = blockIdx.x * blockDim.x + threadIdx.x;
    int stride = gridDim.x * blockDim.x;
    for (int i = idx; i < kN * 32; i += stride) g_agg0[i] = 0.f;
    for (int i = idx; i < kN * 16; i += stride) g_agg1[i] = 0.f;
    for (int i = idx; i < kN; i += stride) g_deg[i] = 0.f;
    if (idx < 64) g_bn0[idx] = 0.f;
    if (idx < 32) g_bn1[idx] = 0.f;
}

__global__ void convert_kernel(const float* __restrict__ W2_0,
                               const float* __restrict__ W2_1) {
    int idx = blockIdx.x * blockDim.x + threadIdx.x;
    int stride = gridDim.x * blockDim.x;
    for (int i = idx; i < kM * kM; i += stride) {
        g_W2bf0[i] = __float2bfloat16(W2_0[i]);
        g_W2bf1[i] = __float2bfloat16(W2_1[i]);
    }
}

__global__ void deg_kernel(const int* __restrict__ dst) {
    int e = blockIdx.x * blockDim.x + threadIdx.x;
    if (e < kE) atomicAdd(&g_deg[dst[e]], 1.0f);
}

// ---------------- fused edge kernel (warp-specialized) ----------------
// Per CTA: 128 edges, 512 threads = 16 warps, 1 CTA/SM (smem 223KB).
// Warps 0-7: MMA consumers (warp w owns rows [16w,16w+16)), identical math to
// the R11 kernel. Warps 8-15: producers staging W2 column-block K-halves into
// a double-buffered sB, overlapped with MMA. One __syncthreads per K-half
// chunk ping-pongs buffers (32 chunks total for FIN=16; 64 for FIN=32).
template <int FIN, int FOUT>
__global__ __launch_bounds__(512, 1)
void edge_kernel(const float* __restrict__ x_in,
                 const float* __restrict__ ea,
                 const float* __restrict__ W1,
                 const float* __restrict__ b1,
                 const float* __restrict__ b2,
                 const int* __restrict__ src,
                 const int* __restrict__ dst) {
    constexpr int TE = 128;          // edges per CTA
    constexpr int NT = 512;          // threads (16 warps)
    constexpr int KH = 256;          // K-half rows per staged chunk
    constexpr int NCHUNK = FIN * 2;  // total chunks
    constexpr int UPAD = 520;        // bf16 row stride for U
    constexpr int BPAD = FOUT + 8;   // bf16 row stride for B tile (16B-aligned rows)
    constexpr int CPAD = FOUT + 4;   // fp32 row stride for C scratch
    constexpr int SEGS = FOUT / 8;   // 16-byte segments per B row

    extern __shared__ char smem_raw[];
    __nv_bfloat16* sU = (__nv_bfloat16*)smem_raw;             // TE*UPAD
    __nv_bfloat16* sB = sU + TE * UPAD;                       // 2 * KH*BPAD (double buffer)
    float* sC   = (float*)(sB + 2 * KH * BPAD);               // 8*16*CPAD
    float* sMsg = sC + 8 * 16 * CPAD;                         // TE*FOUT
    float* sXS  = sMsg + TE * FOUT;                           // TE*FIN
    float* sEA  = sXS + TE * FIN;                             // TE*8
    float* sB2  = sEA + TE * 8;                               // kM

    // device-global selection happens here, in device code
    const float* x = (FIN == 32) ? (const float*)g_x1 : x_in;
    float* agg = (FOUT == 32) ? (float*)g_agg0 : (float*)g_agg1;
    const __nv_bfloat16* W2bf = (FOUT == 32) ? (const __nv_bfloat16*)g_W2bf0
                                             : (const __nv_bfloat16*)g_W2bf1;

    int tid = threadIdx.x;
    int w = tid >> 5, lane = tid & 31;
    bool isMMA = (w < 8);
    int ptid = tid - 256;            // producer-local tid in [0,256) for warps 8-15
    int e0 = blockIdx.x * TE;

    // stage edge_attr, gathered source features, b2; zero msg (all 512 threads)
    for (int idx = tid; idx < TE * 8; idx += NT) {
        int r = idx >> 3;
        int e = e0 + r;
        sEA[idx] = (e < kE) ? ea[e * 8 + (idx & 7)] : 0.f;
    }
    for (int idx = tid; idx < TE * FIN; idx += NT) {
        int r = idx / FIN;
        int e = e0 + r;
        sXS[idx] = (e < kE) ? x[src[e] * FIN + (idx % FIN)] : 0.f;
    }
    for (int idx = tid; idx < TE * FOUT; idx += NT) sMsg[idx] = 0.f;
    for (int idx = tid; idx < kM; idx += NT) sB2[idx] = b2[idx];
    __syncthreads();

    // Split phase: MMA warps compute U; producer warps prestage chunk 0.
    if (isMMA) {
        // U = lrelu(ea @ W1 + b1) -> bf16  (256 threads)
        for (int idx = tid; idx < TE * kM; idx += 256) {
            int r = idx >> 9;
            int k = idx & 511;
            float v = b1[k];
            const float* eaR = sEA + r * 8;
#pragma unroll
            for (int j = 0; j < 8; j++) v += eaR[j] * W1[j * kM + k];
            v = (v >= 0.f) ? v : 0.01f * v;
            sU[r * UPAD + k] = __float2bfloat16(v);
        }
    } else {
        // prestage chunk 0 (i=0, h=0) into buffer 0
        for (int idx = ptid; idx < KH * SEGS; idx += 256) {
            int k = idx / SEGS;
            int seg = idx % SEGS;
            const uint4* srcp = (const uint4*)(W2bf + k * kM + 0) + seg;
            *((uint4*)(sB + k * BPAD) + seg) = *srcp;
        }
    }
    __syncthreads();  // U ready; chunk 0 ready

    wmma::fragment<wmma::accumulator, 16, 16, 16, float> cfr[FOUT / 16];

    for (int c = 0; c < NCHUNK; c++) {
        int i = c >> 1;
        int h = c & 1;
        __nv_bfloat16* bufCur = sB + (c & 1 ? KH * BPAD : 0);

        if (isMMA) {
            if (h == 0) {
#pragma unroll
                for (int t = 0; t < FOUT / 16; t++) wmma::fill_fragment(cfr[t], 0.f);
            }
            const __nv_bfloat16* aBase = sU + (w * 16) * UPAD + h * KH;
            for (int k = 0; k < KH; k += 16) {
                wmma::fragment<wmma::matrix_a, 16, 16, 16, __nv_bfloat16, wmma::row_major> afr;
                wmma::load_matrix_sync(afr, aBase + k, UPAD);
#pragma unroll
                for (int t = 0; t < FOUT / 16; t++) {
                    wmma::fragment<wmma::matrix_b, 16, 16, 16, __nv_bfloat16, wmma::row_major> bfr;
                    wmma::load_matrix_sync(bfr, bufCur + k * BPAD + t * 16, BPAD);
                    wmma::mma_sync(cfr[t], afr, bfr, cfr[t]);
                }
            }
            if (h == 1) {
                // epilogue for feature i: sC is per-warp scratch (own rows only)
                float* cW = sC + w * 16 * CPAD;
#pragma unroll
                for (int t = 0; t < FOUT / 16; t++)
                    wmma::store_matrix_sync(cW + t * 16, cfr[t], CPAD, wmma::mem_row_major);
                __syncwarp();
                for (int idx = lane; idx < 16 * FOUT; idx += 32) {
                    int r = idx / FOUT;
                    int cc = idx % FOUT;
                    int row = w * 16 + r;
                    sMsg[row * FOUT + cc] += sXS[row * FIN + i] * (cW[r * CPAD + cc] + sB2[i * FOUT + cc]);
                }
                __syncwarp();
            }
        } else if (c + 1 < NCHUNK) {
            // stage chunk c+1 into the other buffer
            int ni = (c + 1) >> 1;
            int nh = (c + 1) & 1;
            __nv_bfloat16* bufNxt = sB + ((c + 1) & 1 ? KH * BPAD : 0);
            for (int idx = ptid; idx < KH * SEGS; idx += 256) {
                int k = idx / SEGS;
                int seg = idx % SEGS;
                const uint4* srcp = (const uint4*)(W2bf + (nh * KH + k) * kM + ni * FOUT) + seg;
                *((uint4*)(bufNxt + k * BPAD) + seg) = *srcp;
            }
        }
        __syncthreads();  // next chunk staged; current buffer free for re-stage
    }

    // scatter-add messages at destination nodes (all 512 threads)
    for (int idx = tid; idx < TE * FOUT; idx += NT) {
        int r = idx / FOUT;
        int e = e0 + r;
        if (e < kE) atomicAdd(&agg[dst[e] * FOUT + (idx % FOUT)], sMsg[idx]);
    }
}

// ---------------- combine: v = agg/deg + x@root + bias; accumulate BN stats ----------------
template <int FIN, int FOUT>
__global__ void combine_kernel(const float* __restrict__ x_in,
                               const float* __restrict__ root,
                               const float* __restrict__ bias,
                               float* __restrict__ vout_param) {
    constexpr int NPB = 256 / FOUT;          // nodes per block-pass
    __shared__ float sroot[FIN * FOUT];
    __shared__ float sred[256];

    const float* agg = (FOUT == 32) ? (const float*)g_agg0 : (const float*)g_agg1;
    const float* x = (FIN == 32) ? (const float*)g_x1 : x_in;
    float* vout = (FOUT == 32) ? (float*)g_x1 : vout_param;
    float* bnsum = (FOUT == 32) ? (float*)g_bn0 : (float*)g_bn1;

    int tid = threadIdx.x;
    int o = tid % FOUT;
    int nl = tid / FOUT;
    for (int idx = tid; idx < FIN * FOUT; idx += 256) sroot[idx] = root[idx];
    __syncthreads();

    float s = 0.f, ss = 0.f;
    float bo = bias[o];
    int nblocks = kN / NPB;  // exact: 50000 % 8 == 0, % 16 == 0
    for (int nb = blockIdx.x; nb < nblocks; nb += gridDim.x) {
        int n = nb * NPB + nl;
        float v = agg[n * FOUT + o] / fmaxf(g_deg[n], 1.f);
        const float* xr = x + n * FIN;
#pragma unroll
        for (int i = 0; i < FIN; i++) v += xr[i] * sroot[i * FOUT + o];
        v += bo;
        vout[n * FOUT + o] = v;
        s += v;
        ss += v * v;
    }
    // block-reduce over the node dimension, per channel
    sred[tid] = s;
    __syncthreads();
    for (int m = NPB / 2; m > 0; m >>= 1) {
        if (nl < m) sred[tid] += sred[tid + m * FOUT];
        __syncthreads();
    }
    if (nl == 0) atomicAdd(&bnsum[o], sred[tid]);
    __syncthreads();
    sred[tid] = ss;
    __syncthreads();
    for (int m = NPB / 2; m > 0; m >>= 1) {
        if (nl < m) sred[tid] += sred[tid + m * FOUT];
        __syncthreads();
    }
    if (nl == 0) atomicAdd(&bnsum[FOUT + o], sred[tid]);
}

// ---------------- finalize: batchnorm (+ optional lrelu), in place ----------------
template <int FOUT, bool LRELU>
__global__ void finalize_kernel(float* __restrict__ v_param,
                                const float* __restrict__ gamma,
                                const float* __restrict__ beta) {
    float* v = (FOUT == 32) ? (float*)g_x1 : v_param;
    const float* bnsum = (FOUT == 32) ? (const float*)g_bn0 : (const float*)g_bn1;
    int idx = blockIdx.x * blockDim.x + threadIdx.x;
    if (idx >= kN * FOUT) return;
    int o = idx % FOUT;
    float mu = bnsum[o] * (1.f / kN);
    float var = bnsum[FOUT + o] * (1.f / kN) - mu * mu;
    float sc = rsqrtf(var + kEps) * gamma[o];
    float val = (v[idx] - mu) * sc + beta[o];
    if (LRELU) val = (val >= 0.f) ? val : 0.01f * val;
    v[idx] = val;
}

// ---------------- launch ----------------
extern "C" void kernel_launch(void* const* d_in, const int* in_sizes, int n_in,
                              void* d_out, int out_size) {
    (void)n_in; (void)out_size;
    // Input-order dispatch (confirmed: harness uses dict-insertion order;
    // keep signature-order fallback for robustness).
    const bool dictOrder = (in_sizes[2] == 2 * kE);
    const int wbase = dictOrder ? 3 : 2;      // index of W1_0
    const int eiIdx = dictOrder ? 2 : 18;     // index of edge_index

    const float* x      = (const float*)d_in[0];
    const float* ea     = (const float*)d_in[1];
    const float* W1_0   = (const float*)d_in[wbase + 0];
    const float* b1_0   = (const float*)d_in[wbase + 1];
    const float* W2_0   = (const float*)d_in[wbase + 2];
    const float* b2_0   = (const float*)d_in[wbase + 3];
    const float* root_0 = (const float*)d_in[wbase + 4];
    const float* bias_0 = (const float*)d_in[wbase + 5];
    const float* gamma_0 = (const float*)d_in[wbase + 6];
    const float* beta_0  = (const float*)d_in[wbase + 7];
    const float* W1_1   = (const float*)d_in[wbase + 8];
    const float* b1_1   = (const float*)d_in[wbase + 9];
    const float* W2_1   = (const float*)d_in[wbase + 10];
    const float* b2_1   = (const float*)d_in[wbase + 11];
    const float* root_1 = (const float*)d_in[wbase + 12];
    const float* bias_1 = (const float*)d_in[wbase + 13];
    const float* gamma_1 = (const float*)d_in[wbase + 14];
    const float* beta_1  = (const float*)d_in[wbase + 15];
    const int* ei = (const int*)d_in[eiIdx];
    const int* src = ei;
    const int* dst = ei + kE;
    float* out = (float*)d_out;

    // dynamic SMEM: TE=128, double-buffered KH=256 staging, 16 warps, 1 CTA/SM.
    constexpr int SMEM0 = 128 * 520 * 2 + 2 * 256 * 40 * 2 + 8 * 16 * 36 * 4 +
                          128 * 32 * 4 + 128 * 16 * 4 + 128 * 8 * 4 + kM * 4;  // 223232
    constexpr int SMEM1 = 128 * 520 * 2 + 2 * 256 * 24 * 2 + 8 * 16 * 20 * 4 +
                          128 * 16 * 4 + 128 * 32 * 4 + 128 * 8 * 4 + kM * 4;  // 198656
    cudaFuncSetAttribute(edge_kernel<16, 32>,
                         cudaFuncAttributeMaxDynamicSharedMemorySize, SMEM0);
    cudaFuncSetAttribute(edge_kernel<32, 16>,
                         cudaFuncAttributeMaxDynamicSharedMemorySize, SMEM1);

    constexpr int EDGE_BLOCKS = (kE + 127) / 128;  // 1563

    zero_kernel<<<2048, 256>>>();
    convert_kernel<<<1024, 256>>>(W2_0, W2_1);
    deg_kernel<<<(kE + 255) / 256, 256>>>(dst);

    // ---- layer 0 ----
    edge_kernel<16, 32><<<EDGE_BLOCKS, 512, SMEM0>>>(x, ea, W1_0, b1_0, b2_0, src, dst);
    combine_kernel<16, 32><<<1024, 256>>>(x, root_0, bias_0, nullptr);
    finalize_kernel<32, true><<<(kN * 32 + 255) / 256, 256>>>(nullptr, gamma_0, beta_0);

    // ---- layer 1 ----
    edge_kernel<32, 16><<<EDGE_BLOCKS, 512, SMEM1>>>(nullptr, ea, W1_1, b1_1, b2_1, src, dst);
    combine_kernel<32, 16><<<1024, 256>>>(nullptr, root_1, bias_1, out);
    finalize_kernel<16, false><<<(kN * 16 + 255) / 256, 256>>>(out, gamma_1, beta_1);
}